// round 3
// baseline (speedup 1.0000x reference)
#include <cuda_runtime.h>

#define N_NODES 40000
#define N_EDGES 640000
#define CH 128
#define NCLS 40
#define NB_SCAN ((N_NODES + 1023) / 1024)  // 40

// ---- scratch (static __device__ arrays: no allocations allowed) ----
// float4-typed => guaranteed 16B alignment for vector ld/st.
__device__ float4 g_b0[N_NODES * 32];
__device__ float4 g_b1[N_NODES * 32];
__device__ float4 g_b2[N_NODES * 32];
__device__ int    g_count[N_NODES];
__device__ int    g_offs[N_NODES];
__device__ int    g_cursor[N_NODES];
__device__ int    g_srcs[N_EDGES];
__device__ int    g_bsums[NB_SCAN];
__device__ int    g_is64;

// pick internal buffer by selector (device-side; avoids cudaGetSymbolAddress)
__device__ __forceinline__ float4* pick_buf(int s) {
    return (s == 0) ? g_b0 : (s == 1) ? g_b1 : g_b2;
}

// ---- edge-index dtype detection + width-aware load ----
// If the [2,E] index tensor is int64 (little-endian, values < 2^31), every odd
// 32-bit word is zero. If int32, odd words are random values in [0, 40000).
__global__ void k_detect(const int* __restrict__ e) {
    if (threadIdx.x == 0 && blockIdx.x == 0) {
        int nz = 0;
        for (int i = 1; i < 256; i += 2) nz |= e[i];
        g_is64 = (nz == 0) ? 1 : 0;
    }
}

__device__ __forceinline__ int ld_idx(const int* __restrict__ e, int pos) {
    int v = g_is64 ? e[2 * pos] : e[pos];
    return min(max(v, 0), N_NODES - 1);   // clamp: never OOB even if detection is wrong
}

// ============================ CSR build ============================

__global__ void k_zero_counts() {
    int i = blockIdx.x * blockDim.x + threadIdx.x;
    if (i < N_NODES) g_count[i] = 0;
}

__global__ void k_hist(const int* __restrict__ e) {
    int i = blockIdx.x * blockDim.x + threadIdx.x;
    if (i < N_EDGES) atomicAdd(&g_count[ld_idx(e, N_EDGES + i)], 1);
}

__global__ void k_scan_block() {
    __shared__ int s[1024];
    int t = threadIdx.x;
    int i = blockIdx.x * 1024 + t;
    int v = (i < N_NODES) ? g_count[i] : 0;
    s[t] = v;
    __syncthreads();
    for (int d = 1; d < 1024; d <<= 1) {
        int add = (t >= d) ? s[t - d] : 0;
        __syncthreads();
        s[t] += add;
        __syncthreads();
    }
    if (i < N_NODES) g_offs[i] = s[t] - v;   // exclusive partial
    if (t == 1023) g_bsums[blockIdx.x] = s[t];
}

__global__ void k_scan_top() {
    if (threadIdx.x == 0) {
        int a = 0;
        for (int b = 0; b < NB_SCAN; b++) { int v = g_bsums[b]; g_bsums[b] = a; a += v; }
    }
}

__global__ void k_scan_add() {
    int i = blockIdx.x * blockDim.x + threadIdx.x;
    if (i < N_NODES) {
        int o = g_offs[i] + g_bsums[i >> 10];
        g_offs[i] = o;
        g_cursor[i] = o;
    }
}

__global__ void k_scatter(const int* __restrict__ e) {
    int i = blockIdx.x * blockDim.x + threadIdx.x;
    if (i < N_EDGES) {
        int d = ld_idx(e, N_EDGES + i);
        int p = atomicAdd(&g_cursor[d], 1);
        g_srcs[p] = ld_idx(e, i);
    }
}

// ========== aggregation: O[n] = X[n] + sum_{e: dst=n} X[src[e]] ==========
// warp-per-node, one float4 per lane (32 lanes x 16B = full 512B row).
// Gather-based: zero float atomics. Writes g_b0.
__global__ void k_agg(const float4* __restrict__ Xext, int src_sel) {
    int warp = (blockIdx.x * blockDim.x + threadIdx.x) >> 5;
    int lane = threadIdx.x & 31;
    if (warp >= N_NODES) return;
    const float4* X4 = (src_sel == 0) ? Xext : g_b2;
    float4 acc = X4[warp * 32 + lane];         // self term (eps = 0)
    int s0 = g_offs[warp];
    int n  = g_count[warp];
    int s_next = (n > 0) ? g_srcs[s0] : 0;
    for (int j = 0; j < n; j++) {
        int s = s_next;
        if (j + 1 < n) s_next = g_srcs[s0 + j + 1];
        float4 v = X4[s * 32 + lane];
        acc.x += v.x; acc.y += v.y; acc.z += v.z; acc.w += v.w;
    }
    g_b0[warp * 32 + lane] = acc;
}

// ========== SGEMM: C[M,ncols] = act(A[M,128] @ W[128,ncols] + bias) ==========
// BM=128, full K=128 resident; A-tile (transposed) + W in dynamic smem;
// 256 threads, 8xTN register tiles.
template<int BN, bool RELU>
__global__ __launch_bounds__(256, 1)
void k_gemm(int src_sel, const float* __restrict__ W,
            const float* __restrict__ bias,
            float* __restrict__ Cext, int dst_sel,
            int ncols, int ldc) {
    constexpr int BNP = BN + 4;
    constexpr int TN  = BN / 16;      // 8 for BN=128, 4 for BN=64
    extern __shared__ float sm[];
    float* AsT = sm;                  // [128][132]  k-major (transposed A tile)
    float* Bs  = sm + 128 * 132;      // [128][BNP]
    int tid = threadIdx.x;
    int m0  = blockIdx.x * 128;

    const float4* A4 = pick_buf(src_sel);

    // ---- load A tile (128 rows x 128 k), transposed into smem ----
#pragma unroll
    for (int it = 0; it < 16; it++) {
        int idx = tid + it * 256;     // 0..4095 float4s
        int m   = idx >> 5;
        int kk  = idx & 31;
        int row = m0 + m;
        float4 v = make_float4(0.f, 0.f, 0.f, 0.f);
        if (row < N_NODES) v = A4[row * 32 + kk];
        int k = kk * 4;
        AsT[(k + 0) * 132 + m] = v.x;
        AsT[(k + 1) * 132 + m] = v.y;
        AsT[(k + 2) * 132 + m] = v.z;
        AsT[(k + 3) * 132 + m] = v.w;
    }
    // ---- load weights (k-major, matches global [128][ncols] layout) ----
    if constexpr (BN == 128) {
#pragma unroll
        for (int it = 0; it < 16; it++) {
            int idx = tid + it * 256;            // 0..4095 float4s
            int k   = idx >> 5;
            int nn  = (idx & 31) * 4;
            float4 v = ((const float4*)W)[idx];
            *(float4*)&Bs[k * BNP + nn] = v;
        }
    } else {
        for (int idx = tid; idx < 128 * BN; idx += 256) {
            int k  = idx / BN;
            int nn = idx % BN;
            Bs[k * BNP + nn] = (nn < ncols) ? W[k * ncols + nn] : 0.f;
        }
    }
    __syncthreads();

    int tx = tid & 15;
    int ty = tid >> 4;
    int r0 = ty * 8;
    int c0 = tx * TN;
    float acc[8][TN];
#pragma unroll
    for (int i = 0; i < 8; i++)
#pragma unroll
        for (int j = 0; j < TN; j++) acc[i][j] = 0.f;

#pragma unroll 8
    for (int k = 0; k < 128; k++) {
        float a[8], b[TN];
        float4 a0 = *(const float4*)&AsT[k * 132 + r0];
        float4 a1 = *(const float4*)&AsT[k * 132 + r0 + 4];
        a[0] = a0.x; a[1] = a0.y; a[2] = a0.z; a[3] = a0.w;
        a[4] = a1.x; a[5] = a1.y; a[6] = a1.z; a[7] = a1.w;
        float4 b0 = *(const float4*)&Bs[k * BNP + c0];
        b[0] = b0.x; b[1] = b0.y; b[2] = b0.z; b[3] = b0.w;
        if constexpr (TN == 8) {
            float4 b1 = *(const float4*)&Bs[k * BNP + c0 + 4];
            b[4] = b1.x; b[5] = b1.y; b[6] = b1.z; b[7] = b1.w;
        }
#pragma unroll
        for (int i = 0; i < 8; i++)
#pragma unroll
            for (int j = 0; j < TN; j++) acc[i][j] += a[i] * b[j];
    }

    float* C = (dst_sel == 3) ? Cext : (float*)pick_buf(dst_sel);

    // ---- epilogue: bias + optional relu ----
#pragma unroll
    for (int i = 0; i < 8; i++) {
        int row = m0 + r0 + i;
        if (row >= N_NODES) continue;
#pragma unroll
        for (int j = 0; j < TN; j++) {
            int c = c0 + j;
            if (c < ncols) {
                float v = acc[i][j] + bias[c];
                if (RELU) v = fmaxf(v, 0.f);
                C[row * ldc + c] = v;
            }
        }
    }
}

// ============================ launch ============================

extern "C" void kernel_launch(void* const* d_in, const int* in_sizes, int n_in,
                              void* d_out, int out_size) {
    const float4* x  = (const float4*)d_in[0];
    const int*    ei = (const int*)d_in[1];     // [2,E]; int32 or int64, auto-detected
    const float* w1a = (const float*)d_in[2];
    const float* b1a = (const float*)d_in[3];
    const float* w1b = (const float*)d_in[4];
    const float* b1b = (const float*)d_in[5];
    const float* w2a = (const float*)d_in[6];
    const float* b2a = (const float*)d_in[7];
    const float* w2b = (const float*)d_in[8];
    const float* b2b = (const float*)d_in[9];
    const float* wlin = (const float*)d_in[10];
    const float* blin = (const float*)d_in[11];
    float* out = (float*)d_out;

    const int smem128 = (128 * 132 + 128 * 132) * 4;  // 135168 B
    const int smem64  = (128 * 132 + 128 * 68) * 4;   // 102400 B
    cudaFuncSetAttribute(k_gemm<128, true>, cudaFuncAttributeMaxDynamicSharedMemorySize, smem128);
    cudaFuncSetAttribute(k_gemm<64, false>, cudaFuncAttributeMaxDynamicSharedMemorySize, smem64);

    const int GEMM_BLOCKS = (N_NODES + 127) / 128;       // 313
    const int EDGE_BLOCKS = (N_EDGES + 255) / 256;       // 2500
    const int NODE_BLOCKS = (N_NODES + 255) / 256;       // 157
    const int AGG_BLOCKS  = (N_NODES * 32 + 255) / 256;  // 5000 (warp per node)

    // CSR build (reused by both layers)
    k_detect<<<1, 32>>>(ei);
    k_zero_counts<<<NODE_BLOCKS, 256>>>();
    k_hist<<<EDGE_BLOCKS, 256>>>(ei);
    k_scan_block<<<NB_SCAN, 1024>>>();
    k_scan_top<<<1, 32>>>();
    k_scan_add<<<NODE_BLOCKS, 256>>>();
    k_scatter<<<EDGE_BLOCKS, 256>>>(ei);

    // layer 1: h1 = relu( relu((x + agg(x)) @ w1a + b1a) @ w1b + b1b )
    k_agg<<<AGG_BLOCKS, 256>>>(x, 0);                                     // -> b0
    k_gemm<128, true><<<GEMM_BLOCKS, 256, smem128>>>(0, w1a, b1a, nullptr, 1, 128, 128);
    k_gemm<128, true><<<GEMM_BLOCKS, 256, smem128>>>(1, w1b, b1b, nullptr, 2, 128, 128);

    // layer 2
    k_agg<<<AGG_BLOCKS, 256>>>(x, 2);                                     // src=b2 -> b0
    k_gemm<128, true><<<GEMM_BLOCKS, 256, smem128>>>(0, w2a, b2a, nullptr, 1, 128, 128);
    k_gemm<128, true><<<GEMM_BLOCKS, 256, smem128>>>(1, w2b, b2b, nullptr, 2, 128, 128);

    // classifier: out = h2 @ wlin + blin
    k_gemm<64, false><<<GEMM_BLOCKS, 256, smem64>>>(2, wlin, blin, out, 3, NCLS, NCLS);
}

// round 7
// speedup vs baseline: 1.2148x; 1.2148x over previous
#include <cuda_runtime.h>
#include <cuda_bf16.h>
#include <cstdint>

#define N_NODES 40000
#define N_EDGES 640000
#define CH 128
#define NCLS 40
#define NB_SCAN ((N_NODES + 1023) / 1024)  // 40

// ---- scratch (static __device__ arrays; no allocations allowed) ----
__device__ float4 g_b0[N_NODES * 32];
__device__ float4 g_b1[N_NODES * 32];
__device__ float4 g_b2[N_NODES * 32];
__device__ int    g_count[N_NODES];
__device__ int    g_offs[N_NODES];
__device__ int    g_cursor[N_NODES];
__device__ int    g_srcs[N_EDGES];
__device__ int    g_bsums[NB_SCAN];
__device__ int    g_is64;

__device__ __forceinline__ float4* pick_buf(int s) {
    return (s == 0) ? g_b0 : (s == 1) ? g_b1 : g_b2;
}

__device__ __forceinline__ uint32_t smem_u32(const void* p) {
    uint32_t a;
    asm("{ .reg .u64 t; cvta.to.shared.u64 t, %1; cvt.u32.u64 %0, t; }" : "=r"(a) : "l"(p));
    return a;
}

// ---- edge-index dtype detection + width-aware load ----
__global__ void k_detect(const int* __restrict__ e) {
    if (threadIdx.x == 0 && blockIdx.x == 0) {
        int nz = 0;
        for (int i = 1; i < 256; i += 2) nz |= e[i];
        g_is64 = (nz == 0) ? 1 : 0;
    }
}
__device__ __forceinline__ int ld_idx(const int* __restrict__ e, int pos) {
    int v = g_is64 ? e[2 * pos] : e[pos];
    return min(max(v, 0), N_NODES - 1);
}

// ============================ CSR build ============================
__global__ void k_zero_counts() {
    int i = blockIdx.x * blockDim.x + threadIdx.x;
    if (i < N_NODES) g_count[i] = 0;
}
__global__ void k_hist(const int* __restrict__ e) {
    int i = blockIdx.x * blockDim.x + threadIdx.x;
    if (i < N_EDGES) atomicAdd(&g_count[ld_idx(e, N_EDGES + i)], 1);
}
__global__ void k_scan_block() {
    __shared__ int s[1024];
    int t = threadIdx.x;
    int i = blockIdx.x * 1024 + t;
    int v = (i < N_NODES) ? g_count[i] : 0;
    s[t] = v;
    __syncthreads();
    for (int d = 1; d < 1024; d <<= 1) {
        int add = (t >= d) ? s[t - d] : 0;
        __syncthreads();
        s[t] += add;
        __syncthreads();
    }
    if (i < N_NODES) g_offs[i] = s[t] - v;
    if (t == 1023) g_bsums[blockIdx.x] = s[t];
}
__global__ void k_scan_top() {
    if (threadIdx.x == 0) {
        int a = 0;
        for (int b = 0; b < NB_SCAN; b++) { int v = g_bsums[b]; g_bsums[b] = a; a += v; }
    }
}
__global__ void k_scan_add() {
    int i = blockIdx.x * blockDim.x + threadIdx.x;
    if (i < N_NODES) {
        int o = g_offs[i] + g_bsums[i >> 10];
        g_offs[i] = o;
        g_cursor[i] = o;
    }
}
__global__ void k_scatter(const int* __restrict__ e) {
    int i = blockIdx.x * blockDim.x + threadIdx.x;
    if (i < N_EDGES) {
        int d = ld_idx(e, N_EDGES + i);
        int p = atomicAdd(&g_cursor[d], 1);
        g_srcs[p] = ld_idx(e, i);
    }
}

// ========== aggregation: b0[n] = X[n] + sum_{e: dst=n} X[src[e]] ==========
__global__ void k_agg(const float4* __restrict__ Xext, int src_sel) {
    int warp = (blockIdx.x * blockDim.x + threadIdx.x) >> 5;
    int lane = threadIdx.x & 31;
    if (warp >= N_NODES) return;
    const float4* X4 = (src_sel == 0) ? Xext : g_b2;
    float4 acc = X4[warp * 32 + lane];
    int s0 = g_offs[warp];
    int n  = g_count[warp];
    int s_next = (n > 0) ? g_srcs[s0] : 0;
    for (int j = 0; j < n; j++) {
        int s = s_next;
        if (j + 1 < n) s_next = g_srcs[s0 + j + 1];
        float4 v = X4[s * 32 + lane];
        acc.x += v.x; acc.y += v.y; acc.z += v.z; acc.w += v.w;
    }
    g_b0[warp * 32 + lane] = acc;
}

// ========== bf16 HMMA GEMM: C = relu(A[M,128] @ W[128,128] + bias) ==========
// mma.sync m16n8k16 bf16 with 3-product split: D = Ah*Bh + Ah*Bl + Al*Bh.
// BM=BN=128, K=128 resident. 8 warps (2m x 4n), warp tile 64x32.
#define LDA 136   // bf16 elements per smem row (128 + 8 pad) -> 272B stride

__device__ __forceinline__ uint32_t pack_bf2(__nv_bfloat16 a, __nv_bfloat16 b) {
    __nv_bfloat162 p(a, b);
    return *(uint32_t*)&p;
}
__device__ __forceinline__ void ldm_x4(uint32_t* r, uint32_t addr) {
    asm volatile("ldmatrix.sync.aligned.m8n8.x4.shared.b16 {%0,%1,%2,%3}, [%4];"
        : "=r"(r[0]), "=r"(r[1]), "=r"(r[2]), "=r"(r[3]) : "r"(addr));
}
__device__ __forceinline__ void ldm_x2(uint32_t* r, uint32_t addr) {
    asm volatile("ldmatrix.sync.aligned.m8n8.x2.shared.b16 {%0,%1}, [%2];"
        : "=r"(r[0]), "=r"(r[1]) : "r"(addr));
}
__device__ __forceinline__ void mma_bf16(float* c, const uint32_t* a, const uint32_t* b) {
    asm volatile(
        "mma.sync.aligned.m16n8k16.row.col.f32.bf16.bf16.f32 "
        "{%0,%1,%2,%3}, {%4,%5,%6,%7}, {%8,%9}, {%0,%1,%2,%3};"
        : "+f"(c[0]), "+f"(c[1]), "+f"(c[2]), "+f"(c[3])
        : "r"(a[0]), "r"(a[1]), "r"(a[2]), "r"(a[3]), "r"(b[0]), "r"(b[1]));
}

__global__ __launch_bounds__(256, 1)
void k_gemm_mma(int src_sel, const float* __restrict__ W,
                const float* __restrict__ bias, int dst_sel) {
    extern __shared__ char sm[];
    // layout (all 16B-aligned): bias[128]f32 | Ah | Al | Bh | Bl  (each 128*LDA bf16)
    const int SZ = 128 * LDA * 2;             // 34816 B
    const int OFF_BIAS = 0, OFF_AH = 512, OFF_AL = OFF_AH + SZ;
    const int OFF_BH = OFF_AL + SZ, OFF_BL = OFF_BH + SZ;
    float* sbias = (float*)(sm + OFF_BIAS);
    __nv_bfloat16* Ah = (__nv_bfloat16*)(sm + OFF_AH);
    __nv_bfloat16* Al = (__nv_bfloat16*)(sm + OFF_AL);
    __nv_bfloat16* Bh = (__nv_bfloat16*)(sm + OFF_BH);
    __nv_bfloat16* Bl = (__nv_bfloat16*)(sm + OFF_BL);

    const int tid = threadIdx.x, lane = tid & 31, wid = tid >> 5;
    const int m0 = blockIdx.x * 128;
    if (tid < 128) sbias[tid] = bias[tid];

    // ---- A: fp32 [row][k] -> hi/lo bf16 [row][k] (k contiguous) ----
    const float4* A4 = pick_buf(src_sel);
#pragma unroll
    for (int it = 0; it < 16; it++) {
        int idx = tid + it * 256;             // 0..4095 float4s
        int r  = idx >> 5;
        int kk = idx & 31;                    // float4 index along k
        int row = m0 + r;
        float4 v = make_float4(0.f, 0.f, 0.f, 0.f);
        if (row < N_NODES) v = A4[row * 32 + kk];
        __nv_bfloat16 h0 = __float2bfloat16(v.x), h1 = __float2bfloat16(v.y);
        __nv_bfloat16 h2 = __float2bfloat16(v.z), h3 = __float2bfloat16(v.w);
        uint2 uh, ul;
        uh.x = pack_bf2(h0, h1); uh.y = pack_bf2(h2, h3);
        ul.x = pack_bf2(__float2bfloat16(v.x - __bfloat162float(h0)),
                        __float2bfloat16(v.y - __bfloat162float(h1)));
        ul.y = pack_bf2(__float2bfloat16(v.z - __bfloat162float(h2)),
                        __float2bfloat16(v.w - __bfloat162float(h3)));
        int off = r * LDA + kk * 4;
        *(uint2*)&Ah[off] = uh;
        *(uint2*)&Al[off] = ul;
    }
    // ---- B: W[k][n] fp32 -> [n][k] hi/lo bf16 (k contiguous) ----
#pragma unroll
    for (int it = 0; it < 16; it++) {
        int idx = tid + it * 256;             // 0..4095 (n, k4) pairs
        int n  = idx & 127;
        int k4 = idx >> 7;                    // 0..31
        float f[4];
#pragma unroll
        for (int j = 0; j < 4; j++) f[j] = W[(k4 * 4 + j) * 128 + n];  // coalesced in n
        __nv_bfloat16 h[4], l[4];
#pragma unroll
        for (int j = 0; j < 4; j++) {
            h[j] = __float2bfloat16(f[j]);
            l[j] = __float2bfloat16(f[j] - __bfloat162float(h[j]));
        }
        uint2 uh, ul;
        uh.x = pack_bf2(h[0], h[1]); uh.y = pack_bf2(h[2], h[3]);
        ul.x = pack_bf2(l[0], l[1]); ul.y = pack_bf2(l[2], l[3]);
        int off = n * LDA + k4 * 4;
        *(uint2*)&Bh[off] = uh;
        *(uint2*)&Bl[off] = ul;
    }
    __syncthreads();

    // ---- warp tiles: 2 (m) x 4 (n); warp covers 64 rows x 32 cols ----
    const int wm = (wid >> 2) * 64;
    const int wn = (wid & 3) * 32;
    const uint32_t sAh = smem_u32(Ah), sAl = smem_u32(Al);
    const uint32_t sBh = smem_u32(Bh), sBl = smem_u32(Bl);

    float acc[4][4][4];
#pragma unroll
    for (int i = 0; i < 4; i++)
#pragma unroll
        for (int j = 0; j < 4; j++)
#pragma unroll
            for (int q = 0; q < 4; q++) acc[i][j][q] = 0.f;

    const int la = lane & 15;                  // A frag row select
    const int lka = (lane >> 4) * 8;           // A frag k-half
    const int lb = lane & 7;                   // B frag row select (n)
    const int lkb = ((lane >> 3) & 1) * 8;     // B frag k-half

#pragma unroll
    for (int kb = 0; kb < 8; kb++) {           // k16 steps
        uint32_t ah[4][4], al[4][4], bh[4][2], bl[4][2];
#pragma unroll
        for (int mi = 0; mi < 4; mi++) {
            uint32_t off = ((wm + mi * 16 + la) * LDA + kb * 16 + lka) * 2;
            ldm_x4(ah[mi], sAh + off);
            ldm_x4(al[mi], sAl + off);
        }
#pragma unroll
        for (int ni = 0; ni < 4; ni++) {
            uint32_t off = ((wn + ni * 8 + lb) * LDA + kb * 16 + lkb) * 2;
            ldm_x2(bh[ni], sBh + off);
            ldm_x2(bl[ni], sBl + off);
        }
#pragma unroll
        for (int mi = 0; mi < 4; mi++)
#pragma unroll
            for (int ni = 0; ni < 4; ni++) {
                mma_bf16(acc[mi][ni], ah[mi], bh[ni]);   // Ah*Bh
                mma_bf16(acc[mi][ni], ah[mi], bl[ni]);   // Ah*Bl
                mma_bf16(acc[mi][ni], al[mi], bh[ni]);   // Al*Bh
            }
    }

    // ---- epilogue: bias + relu; frag c: {c0,c1}=row lane/4, {c2,c3}=row+8 ----
    float* C = (float*)pick_buf(dst_sel);
#pragma unroll
    for (int mi = 0; mi < 4; mi++) {
        int r_lo = m0 + wm + mi * 16 + (lane >> 2);
        int r_hi = r_lo + 8;
#pragma unroll
        for (int ni = 0; ni < 4; ni++) {
            int col = wn + ni * 8 + (lane & 3) * 2;
            float2 v0, v1;
            v0.x = fmaxf(acc[mi][ni][0] + sbias[col], 0.f);
            v0.y = fmaxf(acc[mi][ni][1] + sbias[col + 1], 0.f);
            v1.x = fmaxf(acc[mi][ni][2] + sbias[col], 0.f);
            v1.y = fmaxf(acc[mi][ni][3] + sbias[col + 1], 0.f);
            if (r_lo < N_NODES) *(float2*)&C[r_lo * 128 + col] = v0;
            if (r_hi < N_NODES) *(float2*)&C[r_hi * 128 + col] = v1;
        }
    }
}

// ========== fp32 FFMA GEMM (classifier only: ncols=40) ==========
template<int BN, bool RELU>
__global__ __launch_bounds__(256, 1)
void k_gemm(int src_sel, const float* __restrict__ W,
            const float* __restrict__ bias,
            float* __restrict__ Cext, int dst_sel,
            int ncols, int ldc) {
    constexpr int BNP = BN + 4;
    constexpr int TN  = BN / 16;
    extern __shared__ float smf[];
    float* AsT = smf;                 // [128][132]
    float* Bs  = smf + 128 * 132;     // [128][BNP]
    int tid = threadIdx.x;
    int m0  = blockIdx.x * 128;
    const float4* A4 = pick_buf(src_sel);

#pragma unroll
    for (int it = 0; it < 16; it++) {
        int idx = tid + it * 256;
        int m   = idx >> 5;
        int kk  = idx & 31;
        int row = m0 + m;
        float4 v = make_float4(0.f, 0.f, 0.f, 0.f);
        if (row < N_NODES) v = A4[row * 32 + kk];
        int k = kk * 4;
        AsT[(k + 0) * 132 + m] = v.x;
        AsT[(k + 1) * 132 + m] = v.y;
        AsT[(k + 2) * 132 + m] = v.z;
        AsT[(k + 3) * 132 + m] = v.w;
    }
    for (int idx = tid; idx < 128 * BN; idx += 256) {
        int k  = idx / BN;
        int nn = idx % BN;
        Bs[k * BNP + nn] = (nn < ncols) ? W[k * ncols + nn] : 0.f;
    }
    __syncthreads();

    int tx = tid & 15, ty = tid >> 4;
    int r0 = ty * 8, c0 = tx * TN;
    float acc[8][TN];
#pragma unroll
    for (int i = 0; i < 8; i++)
#pragma unroll
        for (int j = 0; j < TN; j++) acc[i][j] = 0.f;

#pragma unroll 8
    for (int k = 0; k < 128; k++) {
        float a[8], b[TN];
        float4 a0 = *(const float4*)&AsT[k * 132 + r0];
        float4 a1 = *(const float4*)&AsT[k * 132 + r0 + 4];
        a[0] = a0.x; a[1] = a0.y; a[2] = a0.z; a[3] = a0.w;
        a[4] = a1.x; a[5] = a1.y; a[6] = a1.z; a[7] = a1.w;
        float4 b0 = *(const float4*)&Bs[k * BNP + c0];
        b[0] = b0.x; b[1] = b0.y; b[2] = b0.z; b[3] = b0.w;
#pragma unroll
        for (int i = 0; i < 8; i++)
#pragma unroll
            for (int j = 0; j < TN; j++) acc[i][j] += a[i] * b[j];
    }

    float* C = (dst_sel == 3) ? Cext : (float*)pick_buf(dst_sel);
#pragma unroll
    for (int i = 0; i < 8; i++) {
        int row = m0 + r0 + i;
        if (row >= N_NODES) continue;
#pragma unroll
        for (int j = 0; j < TN; j++) {
            int c = c0 + j;
            if (c < ncols) {
                float v = acc[i][j] + bias[c];
                if (RELU) v = fmaxf(v, 0.f);
                C[row * ldc + c] = v;
            }
        }
    }
}

// ============================ launch ============================
extern "C" void kernel_launch(void* const* d_in, const int* in_sizes, int n_in,
                              void* d_out, int out_size) {
    const float4* x  = (const float4*)d_in[0];
    const int*    ei = (const int*)d_in[1];
    const float* w1a = (const float*)d_in[2];
    const float* b1a = (const float*)d_in[3];
    const float* w1b = (const float*)d_in[4];
    const float* b1b = (const float*)d_in[5];
    const float* w2a = (const float*)d_in[6];
    const float* b2a = (const float*)d_in[7];
    const float* w2b = (const float*)d_in[8];
    const float* b2b = (const float*)d_in[9];
    const float* wlin = (const float*)d_in[10];
    const float* blin = (const float*)d_in[11];
    float* out = (float*)d_out;

    const int smem_mma = 512 + 4 * 128 * LDA * 2;     // 139776 B
    const int smem64   = (128 * 132 + 128 * 68) * 4;  // 102400 B
    cudaFuncSetAttribute(k_gemm_mma,        cudaFuncAttributeMaxDynamicSharedMemorySize, smem_mma);
    cudaFuncSetAttribute(k_gemm<64, false>, cudaFuncAttributeMaxDynamicSharedMemorySize, smem64);

    const int GEMM_BLOCKS = (N_NODES + 127) / 128;       // 313
    const int EDGE_BLOCKS = (N_EDGES + 255) / 256;       // 2500
    const int NODE_BLOCKS = (N_NODES + 255) / 256;       // 157
    const int AGG_BLOCKS  = (N_NODES * 32 + 255) / 256;  // 5000

    // CSR build (reused by both layers)
    k_detect<<<1, 32>>>(ei);
    k_zero_counts<<<NODE_BLOCKS, 256>>>();
    k_hist<<<EDGE_BLOCKS, 256>>>(ei);
    k_scan_block<<<NB_SCAN, 1024>>>();
    k_scan_top<<<1, 32>>>();
    k_scan_add<<<NODE_BLOCKS, 256>>>();
    k_scatter<<<EDGE_BLOCKS, 256>>>(ei);

    // layer 1
    k_agg<<<AGG_BLOCKS, 256>>>(x, 0);                               // -> b0
    k_gemm_mma<<<GEMM_BLOCKS, 256, smem_mma>>>(0, w1a, b1a, 1);     // b0 -> b1
    k_gemm_mma<<<GEMM_BLOCKS, 256, smem_mma>>>(1, w1b, b1b, 2);     // b1 -> b2

    // layer 2
    k_agg<<<AGG_BLOCKS, 256>>>(x, 2);                               // b2 -> b0
    k_gemm_mma<<<GEMM_BLOCKS, 256, smem_mma>>>(0, w2a, b2a, 1);
    k_gemm_mma<<<GEMM_BLOCKS, 256, smem_mma>>>(1, w2b, b2b, 2);

    // classifier
    k_gemm<64, false><<<GEMM_BLOCKS, 256, smem64>>>(2, wlin, blin, out, 3, NCLS, NCLS);
}

// round 8
// speedup vs baseline: 1.8271x; 1.5040x over previous
#include <cuda_runtime.h>
#include <cuda_bf16.h>
#include <cstdint>

#define N_NODES 40000
#define N_EDGES 640000
#define CH 128
#define NCLS 40
#define NB_SCAN ((N_NODES + 1023) / 1024)  // 40

// ---- scratch (static __device__ arrays; no allocations allowed) ----
__device__ float4 g_b0[N_NODES * 32];
__device__ float4 g_b1[N_NODES * 32];
__device__ float4 g_b2[N_NODES * 32];
__device__ int    g_count[N_NODES];
__device__ int    g_offs[N_NODES];
__device__ int    g_cursor[N_NODES];
__device__ int    g_srcs[N_EDGES];
__device__ int    g_bsums[NB_SCAN];
__device__ int    g_is64;

__device__ __forceinline__ float4* pick_buf(int s) {
    return (s == 0) ? g_b0 : (s == 1) ? g_b1 : g_b2;
}

__device__ __forceinline__ uint32_t smem_u32(const void* p) {
    uint32_t a;
    asm("{ .reg .u64 t; cvta.to.shared.u64 t, %1; cvt.u32.u64 %0, t; }" : "=r"(a) : "l"(p));
    return a;
}

// ---- width-aware edge-index load (dtype detected in k_init) ----
__device__ __forceinline__ int ld_idx(const int* __restrict__ e, int pos) {
    int v = g_is64 ? e[2 * pos] : e[pos];
    return min(max(v, 0), N_NODES - 1);
}

// ============================ CSR build ============================
// fused: zero counts + dtype detect
__global__ void k_init(const int* __restrict__ e) {
    int i = blockIdx.x * blockDim.x + threadIdx.x;
    if (i < N_NODES) g_count[i] = 0;
    if (i == 0) {
        int nz = 0;
        for (int j = 1; j < 256; j += 2) nz |= e[j];
        g_is64 = (nz == 0) ? 1 : 0;
    }
}
__global__ void k_hist(const int* __restrict__ e) {
    int i = blockIdx.x * blockDim.x + threadIdx.x;
    if (i < N_EDGES) atomicAdd(&g_count[ld_idx(e, N_EDGES + i)], 1);
}
// shfl-based block scan: 2 barriers instead of 20
__global__ void k_scan_block() {
    __shared__ int wsum[32];
    int t = threadIdx.x;
    int i = blockIdx.x * 1024 + t;
    int lane = t & 31, w = t >> 5;
    int v = (i < N_NODES) ? g_count[i] : 0;
    int s = v;
#pragma unroll
    for (int d = 1; d < 32; d <<= 1) {
        int y = __shfl_up_sync(~0u, s, d);
        if (lane >= d) s += y;
    }
    if (lane == 31) wsum[w] = s;
    __syncthreads();
    if (w == 0) {
        int x = wsum[lane];
#pragma unroll
        for (int d = 1; d < 32; d <<= 1) {
            int y = __shfl_up_sync(~0u, x, d);
            if (lane >= d) x += y;
        }
        wsum[lane] = x;
    }
    __syncthreads();
    int incl = s + ((w > 0) ? wsum[w - 1] : 0);
    if (i < N_NODES) g_offs[i] = incl - v;     // exclusive partial
    if (t == 1023) g_bsums[blockIdx.x] = incl;
}
__global__ void k_scan_top() {
    if (threadIdx.x == 0) {
        int a = 0;
        for (int b = 0; b < NB_SCAN; b++) { int v = g_bsums[b]; g_bsums[b] = a; a += v; }
    }
}
__global__ void k_scan_add() {
    int i = blockIdx.x * blockDim.x + threadIdx.x;
    if (i < N_NODES) {
        int o = g_offs[i] + g_bsums[i >> 10];
        g_offs[i] = o;
        g_cursor[i] = o;
    }
}
__global__ void k_scatter(const int* __restrict__ e) {
    int i = blockIdx.x * blockDim.x + threadIdx.x;
    if (i < N_EDGES) {
        int d = ld_idx(e, N_EDGES + i);
        int p = atomicAdd(&g_cursor[d], 1);
        g_srcs[p] = ld_idx(e, i);
    }
}

// ========== aggregation: b0[n] = X[n] + sum_{e: dst=n} X[src[e]] ==========
// warp-per-node, 2-way ILP on the random row gathers.
__global__ void k_agg(const float4* __restrict__ Xext, int src_sel) {
    int warp = (blockIdx.x * blockDim.x + threadIdx.x) >> 5;
    int lane = threadIdx.x & 31;
    if (warp >= N_NODES) return;
    const float4* X4 = (src_sel == 0) ? Xext : g_b2;
    float4 acc = X4[warp * 32 + lane];
    float4 acc2 = make_float4(0.f, 0.f, 0.f, 0.f);
    int s0 = g_offs[warp];
    int n  = g_count[warp];
    int j = 0;
    for (; j + 1 < n; j += 2) {
        int sA = g_srcs[s0 + j];
        int sB = g_srcs[s0 + j + 1];
        float4 vA = X4[sA * 32 + lane];
        float4 vB = X4[sB * 32 + lane];
        acc.x  += vA.x; acc.y  += vA.y; acc.z  += vA.z; acc.w  += vA.w;
        acc2.x += vB.x; acc2.y += vB.y; acc2.z += vB.z; acc2.w += vB.w;
    }
    if (j < n) {
        int s = g_srcs[s0 + j];
        float4 v = X4[s * 32 + lane];
        acc.x += v.x; acc.y += v.y; acc.z += v.z; acc.w += v.w;
    }
    acc.x += acc2.x; acc.y += acc2.y; acc.z += acc2.z; acc.w += acc2.w;
    g_b0[warp * 32 + lane] = acc;
}

// ========== bf16 HMMA GEMM: C = relu(A[M,128] @ W[128,128] + bias) ==========
// 3-product split: D = Ah*Bh + Ah*Bl + Al*Bh. 512 threads (16 warps, 4/SMSP),
// warp tile 32x32 (mi=2, ni=4), BM=BN=K=128 smem-resident.
#define LDA 136   // bf16 per smem row (128 + 8 pad) -> 272B stride

__device__ __forceinline__ uint32_t pack_bf2(__nv_bfloat16 a, __nv_bfloat16 b) {
    __nv_bfloat162 p(a, b);
    return *(uint32_t*)&p;
}
__device__ __forceinline__ void ldm_x4(uint32_t* r, uint32_t addr) {
    asm volatile("ldmatrix.sync.aligned.m8n8.x4.shared.b16 {%0,%1,%2,%3}, [%4];"
        : "=r"(r[0]), "=r"(r[1]), "=r"(r[2]), "=r"(r[3]) : "r"(addr));
}
__device__ __forceinline__ void ldm_x2(uint32_t* r, uint32_t addr) {
    asm volatile("ldmatrix.sync.aligned.m8n8.x2.shared.b16 {%0,%1}, [%2];"
        : "=r"(r[0]), "=r"(r[1]) : "r"(addr));
}
__device__ __forceinline__ void mma_bf16(float* c, const uint32_t* a, const uint32_t* b) {
    asm volatile(
        "mma.sync.aligned.m16n8k16.row.col.f32.bf16.bf16.f32 "
        "{%0,%1,%2,%3}, {%4,%5,%6,%7}, {%8,%9}, {%0,%1,%2,%3};"
        : "+f"(c[0]), "+f"(c[1]), "+f"(c[2]), "+f"(c[3])
        : "r"(a[0]), "r"(a[1]), "r"(a[2]), "r"(a[3]), "r"(b[0]), "r"(b[1]));
}

__global__ __launch_bounds__(512, 1)
void k_gemm_mma(int src_sel, const float* __restrict__ W,
                const float* __restrict__ bias, int dst_sel) {
    extern __shared__ char sm[];
    const int SZ = 128 * LDA * 2;             // 34816 B per tile
    const int OFF_BIAS = 0, OFF_AH = 512, OFF_AL = OFF_AH + SZ;
    const int OFF_BH = OFF_AL + SZ, OFF_BL = OFF_BH + SZ;
    float* sbias = (float*)(sm + OFF_BIAS);
    __nv_bfloat16* Ah = (__nv_bfloat16*)(sm + OFF_AH);
    __nv_bfloat16* Al = (__nv_bfloat16*)(sm + OFF_AL);
    __nv_bfloat16* Bh = (__nv_bfloat16*)(sm + OFF_BH);
    __nv_bfloat16* Bl = (__nv_bfloat16*)(sm + OFF_BL);

    const int tid = threadIdx.x, lane = tid & 31, wid = tid >> 5;
    const int m0 = blockIdx.x * 128;
    if (tid < 128) sbias[tid] = bias[tid];

    // ---- A: fp32 [row][k] -> hi/lo bf16, k contiguous ----
    const float4* A4 = pick_buf(src_sel);
#pragma unroll
    for (int it = 0; it < 8; it++) {
        int idx = tid + it * 512;             // 0..4095 float4s
        int r  = idx >> 5;
        int kk = idx & 31;
        int row = m0 + r;
        float4 v = make_float4(0.f, 0.f, 0.f, 0.f);
        if (row < N_NODES) v = A4[row * 32 + kk];
        __nv_bfloat16 h0 = __float2bfloat16(v.x), h1 = __float2bfloat16(v.y);
        __nv_bfloat16 h2 = __float2bfloat16(v.z), h3 = __float2bfloat16(v.w);
        uint2 uh, ul;
        uh.x = pack_bf2(h0, h1); uh.y = pack_bf2(h2, h3);
        ul.x = pack_bf2(__float2bfloat16(v.x - __bfloat162float(h0)),
                        __float2bfloat16(v.y - __bfloat162float(h1)));
        ul.y = pack_bf2(__float2bfloat16(v.z - __bfloat162float(h2)),
                        __float2bfloat16(v.w - __bfloat162float(h3)));
        int off = r * LDA + kk * 4;
        *(uint2*)&Ah[off] = uh;
        *(uint2*)&Al[off] = ul;
    }
    // ---- B: W[k][n] fp32 -> [n][k] hi/lo bf16 ----
#pragma unroll
    for (int it = 0; it < 8; it++) {
        int idx = tid + it * 512;             // 0..4095 (n, k4) pairs
        int n  = idx & 127;
        int k4 = idx >> 7;
        float f[4];
#pragma unroll
        for (int j = 0; j < 4; j++) f[j] = W[(k4 * 4 + j) * 128 + n];
        __nv_bfloat16 h[4], l[4];
#pragma unroll
        for (int j = 0; j < 4; j++) {
            h[j] = __float2bfloat16(f[j]);
            l[j] = __float2bfloat16(f[j] - __bfloat162float(h[j]));
        }
        uint2 uh, ul;
        uh.x = pack_bf2(h[0], h[1]); uh.y = pack_bf2(h[2], h[3]);
        ul.x = pack_bf2(l[0], l[1]); ul.y = pack_bf2(l[2], l[3]);
        int off = n * LDA + k4 * 4;
        *(uint2*)&Bh[off] = uh;
        *(uint2*)&Bl[off] = ul;
    }
    __syncthreads();

    // ---- warp tiles: 4 (m) x 4 (n); warp covers 32 rows x 32 cols ----
    const int wm = (wid >> 2) * 32;
    const int wn = (wid & 3) * 32;
    const uint32_t sAh = smem_u32(Ah), sAl = smem_u32(Al);
    const uint32_t sBh = smem_u32(Bh), sBl = smem_u32(Bl);

    float acc[2][4][4];
#pragma unroll
    for (int i = 0; i < 2; i++)
#pragma unroll
        for (int j = 0; j < 4; j++)
#pragma unroll
            for (int q = 0; q < 4; q++) acc[i][j][q] = 0.f;

    const int la = lane & 15;
    const int lka = (lane >> 4) * 8;
    const int lb = lane & 7;
    const int lkb = ((lane >> 3) & 1) * 8;

#pragma unroll
    for (int kb = 0; kb < 8; kb++) {
        uint32_t ah[2][4], al[2][4], bh[4][2], bl[4][2];
#pragma unroll
        for (int mi = 0; mi < 2; mi++) {
            uint32_t off = ((wm + mi * 16 + la) * LDA + kb * 16 + lka) * 2;
            ldm_x4(ah[mi], sAh + off);
            ldm_x4(al[mi], sAl + off);
        }
#pragma unroll
        for (int ni = 0; ni < 4; ni++) {
            uint32_t off = ((wn + ni * 8 + lb) * LDA + kb * 16 + lkb) * 2;
            ldm_x2(bh[ni], sBh + off);
            ldm_x2(bl[ni], sBl + off);
        }
#pragma unroll
        for (int mi = 0; mi < 2; mi++)
#pragma unroll
            for (int ni = 0; ni < 4; ni++) {
                mma_bf16(acc[mi][ni], ah[mi], bh[ni]);   // Ah*Bh
                mma_bf16(acc[mi][ni], ah[mi], bl[ni]);   // Ah*Bl
                mma_bf16(acc[mi][ni], al[mi], bh[ni]);   // Al*Bh
            }
    }

    // ---- epilogue: bias + relu ----
    float* C = (float*)pick_buf(dst_sel);
#pragma unroll
    for (int mi = 0; mi < 2; mi++) {
        int r_lo = m0 + wm + mi * 16 + (lane >> 2);
        int r_hi = r_lo + 8;
#pragma unroll
        for (int ni = 0; ni < 4; ni++) {
            int col = wn + ni * 8 + (lane & 3) * 2;
            float2 v0, v1;
            v0.x = fmaxf(acc[mi][ni][0] + sbias[col], 0.f);
            v0.y = fmaxf(acc[mi][ni][1] + sbias[col + 1], 0.f);
            v1.x = fmaxf(acc[mi][ni][2] + sbias[col], 0.f);
            v1.y = fmaxf(acc[mi][ni][3] + sbias[col + 1], 0.f);
            if (r_lo < N_NODES) *(float2*)&C[r_lo * 128 + col] = v0;
            if (r_hi < N_NODES) *(float2*)&C[r_hi * 128 + col] = v1;
        }
    }
}

// ========== fp32 FFMA GEMM (classifier only: ncols=40) ==========
template<int BN, bool RELU>
__global__ __launch_bounds__(256, 1)
void k_gemm(int src_sel, const float* __restrict__ W,
            const float* __restrict__ bias,
            float* __restrict__ Cext, int dst_sel,
            int ncols, int ldc) {
    constexpr int BNP = BN + 4;
    constexpr int TN  = BN / 16;
    extern __shared__ float smf[];
    float* AsT = smf;                 // [128][132]
    float* Bs  = smf + 128 * 132;     // [128][BNP]
    int tid = threadIdx.x;
    int m0  = blockIdx.x * 128;
    const float4* A4 = pick_buf(src_sel);

#pragma unroll
    for (int it = 0; it < 16; it++) {
        int idx = tid + it * 256;
        int m   = idx >> 5;
        int kk  = idx & 31;
        int row = m0 + m;
        float4 v = make_float4(0.f, 0.f, 0.f, 0.f);
        if (row < N_NODES) v = A4[row * 32 + kk];
        int k = kk * 4;
        AsT[(k + 0) * 132 + m] = v.x;
        AsT[(k + 1) * 132 + m] = v.y;
        AsT[(k + 2) * 132 + m] = v.z;
        AsT[(k + 3) * 132 + m] = v.w;
    }
    for (int idx = tid; idx < 128 * BN; idx += 256) {
        int k  = idx / BN;
        int nn = idx % BN;
        Bs[k * BNP + nn] = (nn < ncols) ? W[k * ncols + nn] : 0.f;
    }
    __syncthreads();

    int tx = tid & 15, ty = tid >> 4;
    int r0 = ty * 8, c0 = tx * TN;
    float acc[8][TN];
#pragma unroll
    for (int i = 0; i < 8; i++)
#pragma unroll
        for (int j = 0; j < TN; j++) acc[i][j] = 0.f;

#pragma unroll 8
    for (int k = 0; k < 128; k++) {
        float a[8], b[TN];
        float4 a0 = *(const float4*)&AsT[k * 132 + r0];
        float4 a1 = *(const float4*)&AsT[k * 132 + r0 + 4];
        a[0] = a0.x; a[1] = a0.y; a[2] = a0.z; a[3] = a0.w;
        a[4] = a1.x; a[5] = a1.y; a[6] = a1.z; a[7] = a1.w;
        float4 b0 = *(const float4*)&Bs[k * BNP + c0];
        b[0] = b0.x; b[1] = b0.y; b[2] = b0.z; b[3] = b0.w;
#pragma unroll
        for (int i = 0; i < 8; i++)
#pragma unroll
            for (int j = 0; j < TN; j++) acc[i][j] += a[i] * b[j];
    }

    float* C = (dst_sel == 3) ? Cext : (float*)pick_buf(dst_sel);
#pragma unroll
    for (int i = 0; i < 8; i++) {
        int row = m0 + r0 + i;
        if (row >= N_NODES) continue;
#pragma unroll
        for (int j = 0; j < TN; j++) {
            int c = c0 + j;
            if (c < ncols) {
                float v = acc[i][j] + bias[c];
                if (RELU) v = fmaxf(v, 0.f);
                C[row * ldc + c] = v;
            }
        }
    }
}

// ============================ launch ============================
extern "C" void kernel_launch(void* const* d_in, const int* in_sizes, int n_in,
                              void* d_out, int out_size) {
    const float4* x  = (const float4*)d_in[0];
    const int*    ei = (const int*)d_in[1];
    const float* w1a = (const float*)d_in[2];
    const float* b1a = (const float*)d_in[3];
    const float* w1b = (const float*)d_in[4];
    const float* b1b = (const float*)d_in[5];
    const float* w2a = (const float*)d_in[6];
    const float* b2a = (const float*)d_in[7];
    const float* w2b = (const float*)d_in[8];
    const float* b2b = (const float*)d_in[9];
    const float* wlin = (const float*)d_in[10];
    const float* blin = (const float*)d_in[11];
    float* out = (float*)d_out;

    const int smem_mma = 512 + 4 * 128 * LDA * 2;     // 139776 B
    const int smem64   = (128 * 132 + 128 * 68) * 4;  // 102400 B
    cudaFuncSetAttribute(k_gemm_mma,        cudaFuncAttributeMaxDynamicSharedMemorySize, smem_mma);
    cudaFuncSetAttribute(k_gemm<64, false>, cudaFuncAttributeMaxDynamicSharedMemorySize, smem64);

    const int GEMM_BLOCKS = (N_NODES + 127) / 128;       // 313
    const int EDGE_BLOCKS = (N_EDGES + 255) / 256;       // 2500
    const int NODE_BLOCKS = (N_NODES + 255) / 256;       // 157
    const int AGG_BLOCKS  = (N_NODES * 32 + 255) / 256;  // 5000

    // CSR build (reused by both layers)
    k_init<<<NODE_BLOCKS, 256>>>(ei);
    k_hist<<<EDGE_BLOCKS, 256>>>(ei);
    k_scan_block<<<NB_SCAN, 1024>>>();
    k_scan_top<<<1, 32>>>();
    k_scan_add<<<NODE_BLOCKS, 256>>>();
    k_scatter<<<EDGE_BLOCKS, 256>>>(ei);

    // layer 1
    k_agg<<<AGG_BLOCKS, 256>>>(x, 0);                               // -> b0
    k_gemm_mma<<<GEMM_BLOCKS, 512, smem_mma>>>(0, w1a, b1a, 1);     // b0 -> b1
    k_gemm_mma<<<GEMM_BLOCKS, 512, smem_mma>>>(1, w1b, b1b, 2);     // b1 -> b2

    // layer 2
    k_agg<<<AGG_BLOCKS, 256>>>(x, 2);                               // b2 -> b0
    k_gemm_mma<<<GEMM_BLOCKS, 512, smem_mma>>>(0, w2a, b2a, 1);
    k_gemm_mma<<<GEMM_BLOCKS, 512, smem_mma>>>(1, w2b, b2b, 2);

    // classifier
    k_gemm<64, false><<<GEMM_BLOCKS, 256, smem64>>>(2, wlin, blin, out, 3, NCLS, NCLS);
}

// round 9
// speedup vs baseline: 2.0549x; 1.1247x over previous
#include <cuda_runtime.h>
#include <cuda_bf16.h>
#include <cstdint>

#define N_NODES 40000
#define N_EDGES 640000
#define CH 128
#define NCLS 40
#define NB_SCAN ((N_NODES + 1023) / 1024)  // 40

// ---- scratch (static __device__ arrays; no allocations allowed) ----
__device__ float4 g_b0[N_NODES * 32];
__device__ float4 g_b1[N_NODES * 32];
__device__ float4 g_b2[N_NODES * 32];
__device__ int    g_count[N_NODES];
__device__ int    g_offs[N_NODES];
__device__ int    g_cursor[N_NODES];
__device__ int    g_srcs[N_EDGES];
__device__ int    g_bsums[NB_SCAN];
__device__ int    g_is64;

__device__ __forceinline__ float4* pick_buf(int s) {
    return (s == 0) ? g_b0 : (s == 1) ? g_b1 : g_b2;
}

__device__ __forceinline__ uint32_t smem_u32(const void* p) {
    uint32_t a;
    asm("{ .reg .u64 t; cvta.to.shared.u64 t, %1; cvt.u32.u64 %0, t; }" : "=r"(a) : "l"(p));
    return a;
}

// ---- width-aware edge-index load (dtype detected in k_init) ----
__device__ __forceinline__ int ld_idx(const int* __restrict__ e, int pos) {
    int v = g_is64 ? e[2 * pos] : e[pos];
    return min(max(v, 0), N_NODES - 1);
}

// ============================ CSR build ============================
__global__ void k_init(const int* __restrict__ e) {
    int i = blockIdx.x * blockDim.x + threadIdx.x;
    if (i < N_NODES) g_count[i] = 0;
    if (i == 0) {
        int nz = 0;
        for (int j = 1; j < 256; j += 2) nz |= e[j];
        g_is64 = (nz == 0) ? 1 : 0;
    }
}
__global__ void k_hist(const int* __restrict__ e) {
    int i = blockIdx.x * blockDim.x + threadIdx.x;
    if (i < N_EDGES) atomicAdd(&g_count[ld_idx(e, N_EDGES + i)], 1);
}
// shfl-based block scan (writes per-block exclusive partials + block totals)
__global__ void k_scan_block() {
    __shared__ int wsum[32];
    int t = threadIdx.x;
    int i = blockIdx.x * 1024 + t;
    int lane = t & 31, w = t >> 5;
    int v = (i < N_NODES) ? g_count[i] : 0;
    int s = v;
#pragma unroll
    for (int d = 1; d < 32; d <<= 1) {
        int y = __shfl_up_sync(~0u, s, d);
        if (lane >= d) s += y;
    }
    if (lane == 31) wsum[w] = s;
    __syncthreads();
    if (w == 0) {
        int x = wsum[lane];
#pragma unroll
        for (int d = 1; d < 32; d <<= 1) {
            int y = __shfl_up_sync(~0u, x, d);
            if (lane >= d) x += y;
        }
        wsum[lane] = x;
    }
    __syncthreads();
    int incl = s + ((w > 0) ? wsum[w - 1] : 0);
    if (i < N_NODES) g_offs[i] = incl - v;
    if (t == 1023) g_bsums[blockIdx.x] = incl;
}
// fused top-level prefix + add: each 256-block computes sum of bsums[0..chunk)
__global__ void k_scan_add() {
    __shared__ int base_s;
    int b = blockIdx.x;
    int chunk = b >> 2;                     // 1024-chunk id for this 256-block
    if (threadIdx.x < 32) {
        int lane = threadIdx.x;
        int v = 0;
        if (lane < chunk) v = g_bsums[lane];
        if (lane + 32 < chunk) v += g_bsums[lane + 32];
#pragma unroll
        for (int d = 16; d > 0; d >>= 1) v += __shfl_down_sync(~0u, v, d);
        if (lane == 0) base_s = v;
    }
    __syncthreads();
    int i = b * 256 + threadIdx.x;
    if (i < N_NODES) {
        int o = g_offs[i] + base_s;
        g_offs[i] = o;
        g_cursor[i] = o;
    }
}
__global__ void k_scatter(const int* __restrict__ e) {
    int i = blockIdx.x * blockDim.x + threadIdx.x;
    if (i < N_EDGES) {
        int d = ld_idx(e, N_EDGES + i);
        int p = atomicAdd(&g_cursor[d], 1);
        g_srcs[p] = ld_idx(e, i);
    }
}

// ========== aggregation: b0[n] = X[n] + sum_{e: dst=n} X[src[e]] ==========
__global__ void k_agg(const float4* __restrict__ Xext, int src_sel) {
    int warp = (blockIdx.x * blockDim.x + threadIdx.x) >> 5;
    int lane = threadIdx.x & 31;
    if (warp >= N_NODES) return;
    const float4* X4 = (src_sel == 0) ? Xext : g_b2;
    float4 acc = X4[warp * 32 + lane];
    float4 acc2 = make_float4(0.f, 0.f, 0.f, 0.f);
    int s0 = g_offs[warp];
    int n  = g_count[warp];
    int j = 0;
    for (; j + 1 < n; j += 2) {
        int sA = g_srcs[s0 + j];
        int sB = g_srcs[s0 + j + 1];
        float4 vA = X4[sA * 32 + lane];
        float4 vB = X4[sB * 32 + lane];
        acc.x  += vA.x; acc.y  += vA.y; acc.z  += vA.z; acc.w  += vA.w;
        acc2.x += vB.x; acc2.y += vB.y; acc2.z += vB.z; acc2.w += vB.w;
    }
    if (j < n) {
        int s = g_srcs[s0 + j];
        float4 v = X4[s * 32 + lane];
        acc.x += v.x; acc.y += v.y; acc.z += v.z; acc.w += v.w;
    }
    acc.x += acc2.x; acc.y += acc2.y; acc.z += acc2.z; acc.w += acc2.w;
    g_b0[warp * 32 + lane] = acc;
}

// ========== bf16 HMMA GEMM: C = act(A[M,128] @ W[128,ncols] + bias) ==========
// 3-product split: D = Ah*Bh + Ah*Bl + Al*Bh. 512 threads (16 warps).
// BN=128: warp tile 32x32 (ni=4). BN=64 (classifier, ncols=40 padded): 32x16 (ni=2).
#define LDA 136   // bf16 per smem row (128 + 8 pad) -> 272B stride

__device__ __forceinline__ uint32_t pack_bf2(__nv_bfloat16 a, __nv_bfloat16 b) {
    __nv_bfloat162 p(a, b);
    return *(uint32_t*)&p;
}
__device__ __forceinline__ void ldm_x4(uint32_t* r, uint32_t addr) {
    asm volatile("ldmatrix.sync.aligned.m8n8.x4.shared.b16 {%0,%1,%2,%3}, [%4];"
        : "=r"(r[0]), "=r"(r[1]), "=r"(r[2]), "=r"(r[3]) : "r"(addr));
}
__device__ __forceinline__ void ldm_x2(uint32_t* r, uint32_t addr) {
    asm volatile("ldmatrix.sync.aligned.m8n8.x2.shared.b16 {%0,%1}, [%2];"
        : "=r"(r[0]), "=r"(r[1]) : "r"(addr));
}
__device__ __forceinline__ void mma_bf16(float* c, const uint32_t* a, const uint32_t* b) {
    asm volatile(
        "mma.sync.aligned.m16n8k16.row.col.f32.bf16.bf16.f32 "
        "{%0,%1,%2,%3}, {%4,%5,%6,%7}, {%8,%9}, {%0,%1,%2,%3};"
        : "+f"(c[0]), "+f"(c[1]), "+f"(c[2]), "+f"(c[3])
        : "r"(a[0]), "r"(a[1]), "r"(a[2]), "r"(a[3]), "r"(b[0]), "r"(b[1]));
}

template<int BN, bool RELU, bool EXT>
__global__ __launch_bounds__(512, 1)
void k_gemm_mma(int src_sel, const float* __restrict__ W,
                const float* __restrict__ bias,
                float* __restrict__ Cext, int dst_sel, int ncols) {
    extern __shared__ char sm[];
    constexpr int SZA = 128 * LDA * 2;        // 34816 B
    constexpr int SZB = BN * LDA * 2;
    constexpr int NI  = BN / 32;              // warp n-frags (4 or 2)
    const int OFF_AH = 512, OFF_AL = OFF_AH + SZA;
    const int OFF_BH = OFF_AL + SZA, OFF_BL = OFF_BH + SZB;
    float* sbias = (float*)sm;
    __nv_bfloat16* Ah = (__nv_bfloat16*)(sm + OFF_AH);
    __nv_bfloat16* Al = (__nv_bfloat16*)(sm + OFF_AL);
    __nv_bfloat16* Bh = (__nv_bfloat16*)(sm + OFF_BH);
    __nv_bfloat16* Bl = (__nv_bfloat16*)(sm + OFF_BL);

    const int tid = threadIdx.x, lane = tid & 31, wid = tid >> 5;
    const int m0 = blockIdx.x * 128;
    if (tid < BN) sbias[tid] = (tid < ncols) ? bias[tid] : 0.f;

    // ---- A: fp32 [row][k] -> hi/lo bf16, k contiguous ----
    const float4* A4 = pick_buf(src_sel);
#pragma unroll
    for (int it = 0; it < 8; it++) {
        int idx = tid + it * 512;             // 0..4095 float4s
        int r  = idx >> 5;
        int kk = idx & 31;
        int row = m0 + r;
        float4 v = make_float4(0.f, 0.f, 0.f, 0.f);
        if (row < N_NODES) v = A4[row * 32 + kk];
        __nv_bfloat16 h0 = __float2bfloat16(v.x), h1 = __float2bfloat16(v.y);
        __nv_bfloat16 h2 = __float2bfloat16(v.z), h3 = __float2bfloat16(v.w);
        uint2 uh, ul;
        uh.x = pack_bf2(h0, h1); uh.y = pack_bf2(h2, h3);
        ul.x = pack_bf2(__float2bfloat16(v.x - __bfloat162float(h0)),
                        __float2bfloat16(v.y - __bfloat162float(h1)));
        ul.y = pack_bf2(__float2bfloat16(v.z - __bfloat162float(h2)),
                        __float2bfloat16(v.w - __bfloat162float(h3)));
        int off = r * LDA + kk * 4;
        *(uint2*)&Ah[off] = uh;
        *(uint2*)&Al[off] = ul;
    }
    // ---- B: W[k][n] fp32 -> [n][k] hi/lo bf16 (cols >= ncols zero) ----
#pragma unroll
    for (int it = 0; it < BN * 32 / 512; it++) {
        int idx = tid + it * 512;             // (n, k4) pairs
        int n  = idx & (BN - 1);
        int k4 = idx / BN;
        float f[4];
#pragma unroll
        for (int j = 0; j < 4; j++)
            f[j] = (n < ncols) ? W[(k4 * 4 + j) * ncols + n] : 0.f;
        __nv_bfloat16 h[4], l[4];
#pragma unroll
        for (int j = 0; j < 4; j++) {
            h[j] = __float2bfloat16(f[j]);
            l[j] = __float2bfloat16(f[j] - __bfloat162float(h[j]));
        }
        uint2 uh, ul;
        uh.x = pack_bf2(h[0], h[1]); uh.y = pack_bf2(h[2], h[3]);
        ul.x = pack_bf2(l[0], l[1]); ul.y = pack_bf2(l[2], l[3]);
        int off = n * LDA + k4 * 4;
        *(uint2*)&Bh[off] = uh;
        *(uint2*)&Bl[off] = ul;
    }
    __syncthreads();

    // ---- warp tiles: 4 (m) x 4 (n); warp covers 32 rows x BN/4 cols ----
    const int wm = (wid >> 2) * 32;
    const int wn = (wid & 3) * (BN / 4);
    const uint32_t sAh = smem_u32(Ah), sAl = smem_u32(Al);
    const uint32_t sBh = smem_u32(Bh), sBl = smem_u32(Bl);

    float acc[2][NI][4];
#pragma unroll
    for (int i = 0; i < 2; i++)
#pragma unroll
        for (int j = 0; j < NI; j++)
#pragma unroll
            for (int q = 0; q < 4; q++) acc[i][j][q] = 0.f;

    const int la = lane & 15;
    const int lka = (lane >> 4) * 8;
    const int lb = lane & 7;
    const int lkb = ((lane >> 3) & 1) * 8;

#pragma unroll
    for (int kb = 0; kb < 8; kb++) {
        uint32_t ah[2][4], al[2][4], bh[NI][2], bl[NI][2];
#pragma unroll
        for (int mi = 0; mi < 2; mi++) {
            uint32_t off = ((wm + mi * 16 + la) * LDA + kb * 16 + lka) * 2;
            ldm_x4(ah[mi], sAh + off);
            ldm_x4(al[mi], sAl + off);
        }
#pragma unroll
        for (int ni = 0; ni < NI; ni++) {
            uint32_t off = ((wn + ni * 8 + lb) * LDA + kb * 16 + lkb) * 2;
            ldm_x2(bh[ni], sBh + off);
            ldm_x2(bl[ni], sBl + off);
        }
#pragma unroll
        for (int mi = 0; mi < 2; mi++)
#pragma unroll
            for (int ni = 0; ni < NI; ni++) {
                mma_bf16(acc[mi][ni], ah[mi], bh[ni]);   // Ah*Bh
                mma_bf16(acc[mi][ni], ah[mi], bl[ni]);   // Ah*Bl
                mma_bf16(acc[mi][ni], al[mi], bh[ni]);   // Al*Bh
            }
    }

    // ---- epilogue: bias + act ----
#pragma unroll
    for (int mi = 0; mi < 2; mi++) {
        int r_lo = m0 + wm + mi * 16 + (lane >> 2);
        int r_hi = r_lo + 8;
#pragma unroll
        for (int ni = 0; ni < NI; ni++) {
            int col = wn + ni * 8 + (lane & 3) * 2;
            float v00 = acc[mi][ni][0] + sbias[col];
            float v01 = acc[mi][ni][1] + sbias[col + 1];
            float v10 = acc[mi][ni][2] + sbias[col];
            float v11 = acc[mi][ni][3] + sbias[col + 1];
            if (RELU) {
                v00 = fmaxf(v00, 0.f); v01 = fmaxf(v01, 0.f);
                v10 = fmaxf(v10, 0.f); v11 = fmaxf(v11, 0.f);
            }
            if (EXT) {   // guarded scalar stores, ldc = ncols
                if (r_lo < N_NODES) {
                    if (col < ncols)     Cext[r_lo * ncols + col]     = v00;
                    if (col + 1 < ncols) Cext[r_lo * ncols + col + 1] = v01;
                }
                if (r_hi < N_NODES) {
                    if (col < ncols)     Cext[r_hi * ncols + col]     = v10;
                    if (col + 1 < ncols) Cext[r_hi * ncols + col + 1] = v11;
                }
            } else {
                float* C = (float*)pick_buf(dst_sel);
                if (r_lo < N_NODES) *(float2*)&C[r_lo * 128 + col] = make_float2(v00, v01);
                if (r_hi < N_NODES) *(float2*)&C[r_hi * 128 + col] = make_float2(v10, v11);
            }
        }
    }
}

// ============================ launch ============================
extern "C" void kernel_launch(void* const* d_in, const int* in_sizes, int n_in,
                              void* d_out, int out_size) {
    const float4* x  = (const float4*)d_in[0];
    const int*    ei = (const int*)d_in[1];
    const float* w1a = (const float*)d_in[2];
    const float* b1a = (const float*)d_in[3];
    const float* w1b = (const float*)d_in[4];
    const float* b1b = (const float*)d_in[5];
    const float* w2a = (const float*)d_in[6];
    const float* b2a = (const float*)d_in[7];
    const float* w2b = (const float*)d_in[8];
    const float* b2b = (const float*)d_in[9];
    const float* wlin = (const float*)d_in[10];
    const float* blin = (const float*)d_in[11];
    float* out = (float*)d_out;

    const int smem128 = 512 + 2 * 34816 + 2 * (128 * LDA * 2);  // 139776
    const int smem64  = 512 + 2 * 34816 + 2 * (64 * LDA * 2);   // 104960
    cudaFuncSetAttribute((const void*)k_gemm_mma<128, true, false>,
                         cudaFuncAttributeMaxDynamicSharedMemorySize, smem128);
    cudaFuncSetAttribute((const void*)k_gemm_mma<64, false, true>,
                         cudaFuncAttributeMaxDynamicSharedMemorySize, smem64);

    const int GEMM_BLOCKS = (N_NODES + 127) / 128;       // 313
    const int EDGE_BLOCKS = (N_EDGES + 255) / 256;       // 2500
    const int NODE_BLOCKS = (N_NODES + 255) / 256;       // 157
    const int AGG_BLOCKS  = (N_NODES * 32 + 255) / 256;  // 5000

    // CSR build (reused by both layers)
    k_init<<<NODE_BLOCKS, 256>>>(ei);
    k_hist<<<EDGE_BLOCKS, 256>>>(ei);
    k_scan_block<<<NB_SCAN, 1024>>>();
    k_scan_add<<<NODE_BLOCKS, 256>>>();
    k_scatter<<<EDGE_BLOCKS, 256>>>(ei);

    // layer 1
    k_agg<<<AGG_BLOCKS, 256>>>(x, 0);                                           // -> b0
    k_gemm_mma<128, true, false><<<GEMM_BLOCKS, 512, smem128>>>(0, w1a, b1a, nullptr, 1, 128);
    k_gemm_mma<128, true, false><<<GEMM_BLOCKS, 512, smem128>>>(1, w1b, b1b, nullptr, 2, 128);

    // layer 2
    k_agg<<<AGG_BLOCKS, 256>>>(x, 2);                                           // b2 -> b0
    k_gemm_mma<128, true, false><<<GEMM_BLOCKS, 512, smem128>>>(0, w2a, b2a, nullptr, 1, 128);
    k_gemm_mma<128, true, false><<<GEMM_BLOCKS, 512, smem128>>>(1, w2b, b2b, nullptr, 2, 128);

    // classifier: out = h2 @ wlin + blin (HMMA, N padded to 64)
    k_gemm_mma<64, false, true><<<GEMM_BLOCKS, 512, smem64>>>(2, wlin, blin, out, 3, NCLS);
}